// round 2
// baseline (speedup 1.0000x reference)
#include <cuda_runtime.h>

#define N_NODES 50000
#define N_EDGES 800000
#define DIM     128
#define DV      32          // DIM/4 float4 per row
#define EPSN    1e-12f

// ---------------- static device scratch (no allocations allowed) ----------------
__device__ float  g_deg[N_NODES];
__device__ int    g_cnt[N_NODES];
__device__ int    g_cur[N_NODES];
__device__ int    g_rowptr[N_NODES + 1];
__device__ int2   g_edge[N_EDGES];          // packed (col, float_as_int(val))
__device__ float4 g_x0[N_NODES * DV];
__device__ float4 g_x1[N_NODES * DV];
__device__ float  g_colsum[DIM];
__device__ float  g_colsq[DIM];

// ---------------- kernels ----------------

__global__ void k_init()
{
    int i = blockIdx.x * blockDim.x + threadIdx.x;
    if (i < N_NODES) {
        g_cnt[i] = 0;
        g_cur[i] = 0;
    }
    if (i < DIM) {
        g_colsum[i] = 0.0f;
        g_colsq[i]  = 0.0f;
    }
}

__global__ void k_hist(const int* __restrict__ erow)
{
    int e = blockIdx.x * blockDim.x + threadIdx.x;
    if (e < N_EDGES) {
        atomicAdd(&g_cnt[erow[e]], 1);
    }
}

// Single-block exclusive scan of g_cnt -> g_rowptr (50001 entries).
__global__ void k_scan()
{
    __shared__ int sh[1024];
    const int t  = threadIdx.x;
    const int CH = (N_NODES + 1023) / 1024;   // 49
    int beg = t * CH;
    int end = min(beg + CH, N_NODES);

    int s = 0;
    for (int i = beg; i < end; i++) s += g_cnt[i];
    sh[t] = s;
    __syncthreads();
    for (int off = 1; off < 1024; off <<= 1) {
        int v = (t >= off) ? sh[t - off] : 0;
        __syncthreads();
        sh[t] += v;
        __syncthreads();
    }
    int run = (t == 0) ? 0 : sh[t - 1];
    for (int i = beg; i < end; i++) {
        g_rowptr[i] = run;
        run += g_cnt[i];
    }
    if (t == 0) g_rowptr[N_NODES] = N_EDGES;
}

__global__ void k_scatter(const int* __restrict__ erow, const int* __restrict__ ecol,
                          const float* __restrict__ eval)
{
    int e = blockIdx.x * blockDim.x + threadIdx.x;
    if (e < N_EDGES) {
        int r = erow[e];
        int p = g_rowptr[r] + atomicAdd(&g_cur[r], 1);
        g_edge[p] = make_int2(ecol[e], __float_as_int(eval[e]));
    }
}

// deg[row] = sum of vals over the row's CSR segment (contiguous reads). 0 -> 1.
__global__ __launch_bounds__(256) void k_deg()
{
    int gtid = blockIdx.x * blockDim.x + threadIdx.x;
    int row  = gtid >> 5;
    int lane = threadIdx.x & 31;
    if (row >= N_NODES) return;
    int s = g_rowptr[row];
    int e = g_rowptr[row + 1];
    float d = 0.f;
    for (int j = s + lane; j < e; j += 32) d += __int_as_float(g_edge[j].y);
    #pragma unroll
    for (int o = 16; o; o >>= 1) d += __shfl_xor_sync(0xffffffffu, d, o);
    if (lane == 0) g_deg[row] = (d == 0.0f) ? 1.0f : d;
}

// x0 = R * deg^(-1/2), and zero d_out (acc buffer).
__global__ void k_initx(const float4* __restrict__ R, float4* __restrict__ acc)
{
    int i = blockIdx.x * blockDim.x + threadIdx.x;
    if (i < N_NODES * DV) {
        int node = i >> 5;
        float s = rsqrtf(g_deg[node]);
        float4 r = R[i];
        g_x0[i] = make_float4(r.x * s, r.y * s, r.z * s, r.w * s);
        acc[i]  = make_float4(0.f, 0.f, 0.f, 0.f);
    }
}

// One warp per row. Lane-coalesced packed edge loads + shfl broadcast.
// Fused: SpMM, inv-deg scale, L2-norm (shuffle reduce), weighted accumulation.
__global__ __launch_bounds__(256) void k_spmm(int flip, float4* __restrict__ acc, float w)
{
    int gtid = blockIdx.x * blockDim.x + threadIdx.x;
    int row  = gtid >> 5;
    int lane = threadIdx.x & 31;
    if (row >= N_NODES) return;

    const float4* __restrict__ xin  = flip ? g_x1 : g_x0;
    float4*       __restrict__ xout = flip ? g_x0 : g_x1;

    int s = g_rowptr[row];
    int e = g_rowptr[row + 1];

    float ax = 0.f, ay = 0.f, az = 0.f, aw = 0.f;

    for (int base = s; base < e; base += 32) {
        int idx = base + lane;
        int2 ed = (idx < e) ? g_edge[idx] : make_int2(0, 0);
        int n = min(32, e - base);
        int k = 0;
        for (; k + 4 <= n; k += 4) {
            int   c0 = __shfl_sync(0xffffffffu, ed.x, k);
            int   c1 = __shfl_sync(0xffffffffu, ed.x, k + 1);
            int   c2 = __shfl_sync(0xffffffffu, ed.x, k + 2);
            int   c3 = __shfl_sync(0xffffffffu, ed.x, k + 3);
            float v0 = __int_as_float(__shfl_sync(0xffffffffu, ed.y, k));
            float v1 = __int_as_float(__shfl_sync(0xffffffffu, ed.y, k + 1));
            float v2 = __int_as_float(__shfl_sync(0xffffffffu, ed.y, k + 2));
            float v3 = __int_as_float(__shfl_sync(0xffffffffu, ed.y, k + 3));
            float4 p0 = xin[c0 * DV + lane];
            float4 p1 = xin[c1 * DV + lane];
            float4 p2 = xin[c2 * DV + lane];
            float4 p3 = xin[c3 * DV + lane];
            ax += v0 * p0.x; ay += v0 * p0.y; az += v0 * p0.z; aw += v0 * p0.w;
            ax += v1 * p1.x; ay += v1 * p1.y; az += v1 * p1.z; aw += v1 * p1.w;
            ax += v2 * p2.x; ay += v2 * p2.y; az += v2 * p2.z; aw += v2 * p2.w;
            ax += v3 * p3.x; ay += v3 * p3.y; az += v3 * p3.z; aw += v3 * p3.w;
        }
        for (; k < n; k++) {
            int   c = __shfl_sync(0xffffffffu, ed.x, k);
            float v = __int_as_float(__shfl_sync(0xffffffffu, ed.y, k));
            float4 p = xin[c * DV + lane];
            ax += v * p.x; ay += v * p.y; az += v * p.z; aw += v * p.w;
        }
    }

    float id = 1.0f / g_deg[row];
    ax *= id; ay *= id; az *= id; aw *= id;

    float ss = ax * ax + ay * ay + az * az + aw * aw;
    #pragma unroll
    for (int o = 16; o; o >>= 1) ss += __shfl_xor_sync(0xffffffffu, ss, o);

    float nrm = fmaxf(sqrtf(ss), EPSN);
    float sc  = w / nrm;

    int base = row * DV + lane;
    xout[base] = make_float4(ax, ay, az, aw);
    float4 a = acc[base];
    acc[base] = make_float4(a.x + sc * ax, a.y + sc * ay, a.z + sc * az, a.w + sc * aw);
}

// Per-column sum and sum-of-squares partial reduction. blockDim = 128.
__global__ void k_colreduce(const float* __restrict__ acc)
{
    int c = threadIdx.x;
    float s = 0.f, q = 0.f;
    for (int r = blockIdx.x; r < N_NODES; r += gridDim.x) {
        float v = acc[r * DIM + c];
        s += v;
        q += v * v;
    }
    atomicAdd(&g_colsum[c], s);
    atomicAdd(&g_colsq[c], q);
}

__global__ void k_std(float* __restrict__ out)
{
    int i = blockIdx.x * blockDim.x + threadIdx.x;
    if (i < N_NODES * DIM) {
        int c = i & (DIM - 1);
        const float n = (float)N_NODES;
        float mean = g_colsum[c] / n;
        float var  = (g_colsq[c] - n * mean * mean) / (n - 1.0f);
        var = fmaxf(var, 0.0f);
        float sd = sqrtf(var);
        if (sd == 0.0f) sd = 1.0f;
        out[i] = (out[i] - mean) / sd;
    }
}

// ---------------- launcher ----------------

extern "C" void kernel_launch(void* const* d_in, const int* in_sizes, int n_in,
                              void* d_out, int out_size)
{
    const int*   erow = (const int*)d_in[0];
    const int*   ecol = (const int*)d_in[1];
    const float* eval = (const float*)d_in[2];
    const float* R    = (const float*)d_in[3];
    float*       out  = (float*)d_out;

    const float W[4] = {1.0f, 1.0f, 7.81f, 45.28f};

    const int warp_blocks = (N_NODES * 32 + 255) / 256;   // warp-per-row kernels

    k_init<<<(N_NODES + 255) / 256, 256>>>();
    k_hist<<<(N_EDGES + 255) / 256, 256>>>(erow);
    k_scan<<<1, 1024>>>();
    k_scatter<<<(N_EDGES + 255) / 256, 256>>>(erow, ecol, eval);
    k_deg<<<warp_blocks, 256>>>();
    k_initx<<<(N_NODES * DV + 255) / 256, 256>>>((const float4*)R, (float4*)d_out);

    for (int i = 0; i < 4; i++) {
        k_spmm<<<warp_blocks, 256>>>(i & 1, (float4*)d_out, W[i]);
    }

    k_colreduce<<<256, DIM>>>(out);
    k_std<<<(N_NODES * DIM + 255) / 256, 256>>>(out);
}

// round 3
// speedup vs baseline: 1.1681x; 1.1681x over previous
#include <cuda_runtime.h>
#include <cuda_fp16.h>

#define N_NODES 50000
#define N_EDGES 800000
#define DIM     128
#define EPSN    1e-12f
#define XSCALE  8.0f        // global per-iteration rescale (invariant under x/||x||)

// ---------------- static device scratch (no allocations allowed) ----------------
__device__ float  g_deg[N_NODES];
__device__ int    g_cnt[N_NODES];
__device__ int    g_cur[N_NODES];
__device__ int    g_rowptr[N_NODES + 1];
__device__ int2   g_edge[N_EDGES];            // packed (col, float_as_int(val))
__device__ uint2  g_x0[N_NODES * 32];         // fp16 x: 4 halves per uint2, 32 per row
__device__ uint2  g_x1[N_NODES * 32];
__device__ float  g_colsum[DIM];
__device__ float  g_colsq[DIM];

// ---------------- helpers ----------------
__device__ __forceinline__ void unpack4(uint2 p, float& a, float& b, float& c, float& d)
{
    __half2 h0 = *(__half2*)&p.x;
    __half2 h1 = *(__half2*)&p.y;
    float2 f0 = __half22float2(h0);
    float2 f1 = __half22float2(h1);
    a = f0.x; b = f0.y; c = f1.x; d = f1.y;
}

__device__ __forceinline__ uint2 pack4(float a, float b, float c, float d)
{
    __half2 h0 = __floats2half2_rn(a, b);
    __half2 h1 = __floats2half2_rn(c, d);
    uint2 u;
    u.x = *(unsigned*)&h0;
    u.y = *(unsigned*)&h1;
    return u;
}

// ---------------- kernels ----------------

__global__ void k_init()
{
    int i = blockIdx.x * blockDim.x + threadIdx.x;
    if (i < N_NODES) {
        g_cnt[i] = 0;
        g_cur[i] = 0;
    }
    if (i < DIM) {
        g_colsum[i] = 0.0f;
        g_colsq[i]  = 0.0f;
    }
}

__global__ void k_hist(const int* __restrict__ erow)
{
    int e = blockIdx.x * blockDim.x + threadIdx.x;
    if (e < N_EDGES) atomicAdd(&g_cnt[erow[e]], 1);
}

// Single-block exclusive scan of g_cnt -> g_rowptr (50001 entries).
__global__ void k_scan()
{
    __shared__ int sh[1024];
    const int t  = threadIdx.x;
    const int CH = (N_NODES + 1023) / 1024;   // 49
    int beg = t * CH;
    int end = min(beg + CH, N_NODES);

    int s = 0;
    for (int i = beg; i < end; i++) s += g_cnt[i];
    sh[t] = s;
    __syncthreads();
    for (int off = 1; off < 1024; off <<= 1) {
        int v = (t >= off) ? sh[t - off] : 0;
        __syncthreads();
        sh[t] += v;
        __syncthreads();
    }
    int run = (t == 0) ? 0 : sh[t - 1];
    for (int i = beg; i < end; i++) {
        g_rowptr[i] = run;
        run += g_cnt[i];
    }
    if (t == 0) g_rowptr[N_NODES] = N_EDGES;
}

__global__ void k_scatter(const int* __restrict__ erow, const int* __restrict__ ecol,
                          const float* __restrict__ eval)
{
    int e = blockIdx.x * blockDim.x + threadIdx.x;
    if (e < N_EDGES) {
        int r = erow[e];
        int p = g_rowptr[r] + atomicAdd(&g_cur[r], 1);
        g_edge[p] = make_int2(ecol[e], __float_as_int(eval[e]));
    }
}

// deg[row] = sum of vals over the row's CSR segment. 0 -> 1.
__global__ __launch_bounds__(256) void k_deg()
{
    int gtid = blockIdx.x * blockDim.x + threadIdx.x;
    int row  = gtid >> 5;
    int lane = threadIdx.x & 31;
    if (row >= N_NODES) return;
    int s = g_rowptr[row];
    int e = g_rowptr[row + 1];
    float d = 0.f;
    for (int j = s + lane; j < e; j += 32) d += __int_as_float(g_edge[j].y);
    #pragma unroll
    for (int o = 16; o; o >>= 1) d += __shfl_xor_sync(0xffffffffu, d, o);
    if (lane == 0) g_deg[row] = (d == 0.0f) ? 1.0f : d;
}

// x0 = R * deg^(-1/2) stored fp16, and zero d_out (acc buffer).
__global__ void k_initx(const float4* __restrict__ R, float4* __restrict__ acc)
{
    int i = blockIdx.x * blockDim.x + threadIdx.x;
    if (i < N_NODES * 32) {
        int node = i >> 5;
        float s = rsqrtf(g_deg[node]);
        float4 r = R[i];
        g_x0[i] = pack4(r.x * s, r.y * s, r.z * s, r.w * s);
        acc[i]  = make_float4(0.f, 0.f, 0.f, 0.f);
    }
}

// One warp per row. Warp-uniform packed edge loads (coalescer broadcasts),
// fp16 gathers, fp32 accumulation. Fused: SpMM, inv-deg, norm, weighted acc.
__global__ __launch_bounds__(256) void k_spmm(int flip, float4* __restrict__ acc,
                                              float w, int last)
{
    int gtid = blockIdx.x * blockDim.x + threadIdx.x;
    int row  = gtid >> 5;
    int lane = threadIdx.x & 31;
    if (row >= N_NODES) return;

    const uint2* __restrict__ xin  = flip ? g_x1 : g_x0;
    uint2*       __restrict__ xout = flip ? g_x0 : g_x1;

    int s = g_rowptr[row];
    int e = g_rowptr[row + 1];

    float ax = 0.f, ay = 0.f, az = 0.f, aw = 0.f;

    int j = s;
    for (; j + 4 <= e; j += 4) {
        int2 e0 = g_edge[j], e1 = g_edge[j + 1], e2 = g_edge[j + 2], e3 = g_edge[j + 3];
        uint2 p0 = xin[e0.x * 32 + lane];
        uint2 p1 = xin[e1.x * 32 + lane];
        uint2 p2 = xin[e2.x * 32 + lane];
        uint2 p3 = xin[e3.x * 32 + lane];
        float v0 = __int_as_float(e0.y), v1 = __int_as_float(e1.y);
        float v2 = __int_as_float(e2.y), v3 = __int_as_float(e3.y);
        float x0,y0,z0,w0, x1,y1,z1,w1, x2,y2,z2,w2, x3,y3,z3,w3;
        unpack4(p0, x0, y0, z0, w0);
        unpack4(p1, x1, y1, z1, w1);
        unpack4(p2, x2, y2, z2, w2);
        unpack4(p3, x3, y3, z3, w3);
        ax += v0 * x0; ay += v0 * y0; az += v0 * z0; aw += v0 * w0;
        ax += v1 * x1; ay += v1 * y1; az += v1 * z1; aw += v1 * w1;
        ax += v2 * x2; ay += v2 * y2; az += v2 * z2; aw += v2 * w2;
        ax += v3 * x3; ay += v3 * y3; az += v3 * z3; aw += v3 * w3;
    }
    for (; j < e; j++) {
        int2 ed = g_edge[j];
        float v = __int_as_float(ed.y);
        uint2 p = xin[ed.x * 32 + lane];
        float x0,y0,z0,w0;
        unpack4(p, x0, y0, z0, w0);
        ax += v * x0; ay += v * y0; az += v * z0; aw += v * w0;
    }

    float id = 1.0f / g_deg[row];
    ax *= id; ay *= id; az *= id; aw *= id;

    float ss = ax * ax + ay * ay + az * az + aw * aw;
    #pragma unroll
    for (int o = 16; o; o >>= 1) ss += __shfl_xor_sync(0xffffffffu, ss, o);

    float nrm = fmaxf(sqrtf(ss), EPSN);
    float sc  = w / nrm;

    int base = row * 32 + lane;
    if (!last) {
        xout[base] = pack4(ax * XSCALE, ay * XSCALE, az * XSCALE, aw * XSCALE);
    }
    float4 a = acc[base];
    acc[base] = make_float4(a.x + sc * ax, a.y + sc * ay, a.z + sc * az, a.w + sc * aw);
}

// Per-column sum and sum-of-squares partial reduction.
__global__ void k_colreduce(const float* __restrict__ acc)
{
    int c = threadIdx.x;
    float s = 0.f, q = 0.f;
    for (int r = blockIdx.x; r < N_NODES; r += gridDim.x) {
        float v = acc[r * DIM + c];
        s += v;
        q += v * v;
    }
    atomicAdd(&g_colsum[c], s);
    atomicAdd(&g_colsq[c], q);
}

__global__ void k_std(float* __restrict__ out)
{
    int i = blockIdx.x * blockDim.x + threadIdx.x;
    if (i < N_NODES * DIM) {
        int c = i & (DIM - 1);
        const float n = (float)N_NODES;
        float mean = g_colsum[c] / n;
        float var  = (g_colsq[c] - n * mean * mean) / (n - 1.0f);
        var = fmaxf(var, 0.0f);
        float sd = sqrtf(var);
        if (sd == 0.0f) sd = 1.0f;
        out[i] = (out[i] - mean) / sd;
    }
}

// ---------------- launcher ----------------

extern "C" void kernel_launch(void* const* d_in, const int* in_sizes, int n_in,
                              void* d_out, int out_size)
{
    const int*   erow = (const int*)d_in[0];
    const int*   ecol = (const int*)d_in[1];
    const float* eval = (const float*)d_in[2];
    const float* R    = (const float*)d_in[3];
    float*       out  = (float*)d_out;

    const float W[4] = {1.0f, 1.0f, 7.81f, 45.28f};

    const int warp_blocks = (N_NODES * 32 + 255) / 256;

    k_init<<<(N_NODES + 255) / 256, 256>>>();
    k_hist<<<(N_EDGES + 255) / 256, 256>>>(erow);
    k_scan<<<1, 1024>>>();
    k_scatter<<<(N_EDGES + 255) / 256, 256>>>(erow, ecol, eval);
    k_deg<<<warp_blocks, 256>>>();
    k_initx<<<(N_NODES * 32 + 255) / 256, 256>>>((const float4*)R, (float4*)d_out);

    for (int i = 0; i < 4; i++) {
        k_spmm<<<warp_blocks, 256>>>(i & 1, (float4*)d_out, W[i], i == 3);
    }

    k_colreduce<<<256, DIM>>>(out);
    k_std<<<(N_NODES * DIM + 255) / 256, 256>>>(out);
}

// round 4
// speedup vs baseline: 1.2140x; 1.0393x over previous
#include <cuda_runtime.h>
#include <cuda_fp16.h>

#define N_NODES 50000
#define N_EDGES 800000
#define DIM     128
#define EPSN    1e-12f
#define XSCALE  8.0f        // global per-iteration rescale (invariant under x/||x||)

// ---------------- static device scratch (no allocations allowed) ----------------
__device__ float  g_deg[N_NODES];
__device__ int    g_cnt[N_NODES];
__device__ int    g_cur[N_NODES];
__device__ int    g_rowptr[N_NODES + 1];
__device__ int2   g_edge[N_EDGES];            // packed (col, float_as_int(val))
__device__ uint2  g_x0[N_NODES * 32];         // fp16 x: 4 halves per uint2, 32 per row
__device__ uint2  g_x1[N_NODES * 32];
__device__ float  g_colsum[DIM];
__device__ float  g_colsq[DIM];

// ---------------- helpers ----------------
__device__ __forceinline__ void unpack4(uint2 p, float& a, float& b, float& c, float& d)
{
    __half2 h0 = *(__half2*)&p.x;
    __half2 h1 = *(__half2*)&p.y;
    float2 f0 = __half22float2(h0);
    float2 f1 = __half22float2(h1);
    a = f0.x; b = f0.y; c = f1.x; d = f1.y;
}

__device__ __forceinline__ uint2 pack4(float a, float b, float c, float d)
{
    __half2 h0 = __floats2half2_rn(a, b);
    __half2 h1 = __floats2half2_rn(c, d);
    uint2 u;
    u.x = *(unsigned*)&h0;
    u.y = *(unsigned*)&h1;
    return u;
}

// ---------------- kernels ----------------

__global__ void k_init()
{
    int i = blockIdx.x * blockDim.x + threadIdx.x;
    if (i < N_NODES) {
        g_deg[i] = 0.0f;
        g_cnt[i] = 0;
        g_cur[i] = 0;
    }
    if (i < DIM) {
        g_colsum[i] = 0.0f;
        g_colsq[i]  = 0.0f;
    }
}

// Histogram counts AND float degree in one pass.
__global__ void k_hist(const int* __restrict__ erow, const float* __restrict__ eval)
{
    int e = blockIdx.x * blockDim.x + threadIdx.x;
    if (e < N_EDGES) {
        int r = erow[e];
        atomicAdd(&g_cnt[r], 1);
        atomicAdd(&g_deg[r], eval[e]);
    }
}

// x0 = R * deg^(-1/2) stored fp16, zero d_out (acc), and canonicalize deg (0 -> 1).
__global__ void k_initx(const float4* __restrict__ R, float4* __restrict__ acc)
{
    int i = blockIdx.x * blockDim.x + threadIdx.x;
    if (i < N_NODES * 32) {
        int node = i >> 5;
        float d = g_deg[node];
        if (d == 0.0f) d = 1.0f;
        if ((i & 31) == 0) g_deg[node] = d;   // all writers store identical value
        float s = rsqrtf(d);
        float4 r = R[i];
        g_x0[i] = pack4(r.x * s, r.y * s, r.z * s, r.w * s);
        acc[i]  = make_float4(0.f, 0.f, 0.f, 0.f);
    }
}

// Single-block exclusive scan of g_cnt -> g_rowptr (50001 entries).
__global__ void k_scan()
{
    __shared__ int sh[1024];
    const int t  = threadIdx.x;
    const int CH = (N_NODES + 1023) / 1024;   // 49
    int beg = t * CH;
    int end = min(beg + CH, N_NODES);

    int s = 0;
    for (int i = beg; i < end; i++) s += g_cnt[i];
    sh[t] = s;
    __syncthreads();
    for (int off = 1; off < 1024; off <<= 1) {
        int v = (t >= off) ? sh[t - off] : 0;
        __syncthreads();
        sh[t] += v;
        __syncthreads();
    }
    int run = (t == 0) ? 0 : sh[t - 1];
    for (int i = beg; i < end; i++) {
        g_rowptr[i] = run;
        run += g_cnt[i];
    }
    if (t == 0) g_rowptr[N_NODES] = N_EDGES;
}

__global__ void k_scatter(const int* __restrict__ erow, const int* __restrict__ ecol,
                          const float* __restrict__ eval)
{
    int e = blockIdx.x * blockDim.x + threadIdx.x;
    if (e < N_EDGES) {
        int r = erow[e];
        int p = g_rowptr[r] + atomicAdd(&g_cur[r], 1);
        g_edge[p] = make_int2(ecol[e], __float_as_int(eval[e]));
    }
}

// One warp per row. Warp-uniform packed edge loads (coalescer broadcasts).
// Unroll-8 for 8 outstanding 256B gathers per batch. fp16 gathers, fp32 math.
__global__ __launch_bounds__(256) void k_spmm(int flip, float4* __restrict__ acc,
                                              float w, int last)
{
    int gtid = blockIdx.x * blockDim.x + threadIdx.x;
    int row  = gtid >> 5;
    int lane = threadIdx.x & 31;
    if (row >= N_NODES) return;

    const uint2* __restrict__ xin  = flip ? g_x1 : g_x0;
    uint2*       __restrict__ xout = flip ? g_x0 : g_x1;

    int s = g_rowptr[row];
    int e = g_rowptr[row + 1];

    float ax = 0.f, ay = 0.f, az = 0.f, aw = 0.f;

    int j = s;
    for (; j + 8 <= e; j += 8) {
        int2 ed[8];
        uint2 p[8];
        #pragma unroll
        for (int k = 0; k < 8; k++) ed[k] = g_edge[j + k];
        #pragma unroll
        for (int k = 0; k < 8; k++) p[k] = xin[ed[k].x * 32 + lane];
        #pragma unroll
        for (int k = 0; k < 8; k++) {
            float v = __int_as_float(ed[k].y);
            float x0, y0, z0, w0;
            unpack4(p[k], x0, y0, z0, w0);
            ax += v * x0; ay += v * y0; az += v * z0; aw += v * w0;
        }
    }
    if (j + 4 <= e) {
        int2 ed[4];
        uint2 p[4];
        #pragma unroll
        for (int k = 0; k < 4; k++) ed[k] = g_edge[j + k];
        #pragma unroll
        for (int k = 0; k < 4; k++) p[k] = xin[ed[k].x * 32 + lane];
        #pragma unroll
        for (int k = 0; k < 4; k++) {
            float v = __int_as_float(ed[k].y);
            float x0, y0, z0, w0;
            unpack4(p[k], x0, y0, z0, w0);
            ax += v * x0; ay += v * y0; az += v * z0; aw += v * w0;
        }
        j += 4;
    }
    for (; j < e; j++) {
        int2 ed = g_edge[j];
        float v = __int_as_float(ed.y);
        uint2 p = xin[ed.x * 32 + lane];
        float x0, y0, z0, w0;
        unpack4(p, x0, y0, z0, w0);
        ax += v * x0; ay += v * y0; az += v * z0; aw += v * w0;
    }

    float id = 1.0f / g_deg[row];
    ax *= id; ay *= id; az *= id; aw *= id;

    float ss = ax * ax + ay * ay + az * az + aw * aw;
    #pragma unroll
    for (int o = 16; o; o >>= 1) ss += __shfl_xor_sync(0xffffffffu, ss, o);

    float nrm = fmaxf(sqrtf(ss), EPSN);
    float sc  = w / nrm;

    int base = row * 32 + lane;
    if (!last) {
        xout[base] = pack4(ax * XSCALE, ay * XSCALE, az * XSCALE, aw * XSCALE);
    }
    float4 a = acc[base];
    acc[base] = make_float4(a.x + sc * ax, a.y + sc * ay, a.z + sc * az, a.w + sc * aw);
}

// Per-column sum and sum-of-squares partial reduction.
__global__ void k_colreduce(const float* __restrict__ acc)
{
    int c = threadIdx.x;
    float s = 0.f, q = 0.f;
    for (int r = blockIdx.x; r < N_NODES; r += gridDim.x) {
        float v = acc[r * DIM + c];
        s += v;
        q += v * v;
    }
    atomicAdd(&g_colsum[c], s);
    atomicAdd(&g_colsq[c], q);
}

__global__ void k_std(float* __restrict__ out)
{
    int i = blockIdx.x * blockDim.x + threadIdx.x;
    if (i < N_NODES * DIM) {
        int c = i & (DIM - 1);
        const float n = (float)N_NODES;
        float mean = g_colsum[c] / n;
        float var  = (g_colsq[c] - n * mean * mean) / (n - 1.0f);
        var = fmaxf(var, 0.0f);
        float sd = sqrtf(var);
        if (sd == 0.0f) sd = 1.0f;
        out[i] = (out[i] - mean) / sd;
    }
}

// ---------------- launcher ----------------

extern "C" void kernel_launch(void* const* d_in, const int* in_sizes, int n_in,
                              void* d_out, int out_size)
{
    const int*   erow = (const int*)d_in[0];
    const int*   ecol = (const int*)d_in[1];
    const float* eval = (const float*)d_in[2];
    const float* R    = (const float*)d_in[3];
    float*       out  = (float*)d_out;

    const float W[4] = {1.0f, 1.0f, 7.81f, 45.28f};

    const int warp_blocks = (N_NODES * 32 + 255) / 256;

    // Launch order chosen so the 6th launch is SpMM iter 0 (ncu -s 5 -c 1).
    k_init<<<(N_NODES + 255) / 256, 256>>>();                                   // 1
    k_hist<<<(N_EDGES + 255) / 256, 256>>>(erow, eval);                         // 2
    k_initx<<<(N_NODES * 32 + 255) / 256, 256>>>((const float4*)R,
                                                 (float4*)d_out);               // 3
    k_scan<<<1, 1024>>>();                                                      // 4
    k_scatter<<<(N_EDGES + 255) / 256, 256>>>(erow, ecol, eval);                // 5

    for (int i = 0; i < 4; i++) {                                               // 6..9
        k_spmm<<<warp_blocks, 256>>>(i & 1, (float4*)d_out, W[i], i == 3);
    }

    k_colreduce<<<256, DIM>>>(out);
    k_std<<<(N_NODES * DIM + 255) / 256, 256>>>(out);
}

// round 7
// speedup vs baseline: 1.4296x; 1.1777x over previous
#include <cuda_runtime.h>
#include <cuda_fp16.h>

#define N_NODES 50000
#define N_EDGES 800000
#define DIM     128
#define EPSN    1e-12f
#define XSCALE  8.0f        // global per-iteration rescale (invariant under x/||x||)
#define NB      ((N_NODES + 255) / 256)   // 196 scan blocks

// ---------------- static device scratch (no allocations allowed) ----------------
__device__ float  g_deg[N_NODES];
__device__ int    g_cnt[N_NODES];
__device__ int    g_cur[N_NODES];
__device__ int    g_rowptr[N_NODES + 1];
__device__ int    g_bsum[NB];
__device__ int    g_boff[NB];
__device__ int2   g_edge[N_EDGES];            // packed (col, float_as_int(val))
__device__ uint2  g_x0[N_NODES * 32];         // fp16 x: 4 halves per uint2, 32 per row
__device__ uint2  g_x1[N_NODES * 32];
__device__ float  g_colsum[DIM];
__device__ float  g_colsq[DIM];

// ---------------- helpers ----------------
__device__ __forceinline__ void unpack4(uint2 p, float& a, float& b, float& c, float& d)
{
    __half2 h0 = *(__half2*)&p.x;
    __half2 h1 = *(__half2*)&p.y;
    float2 f0 = __half22float2(h0);
    float2 f1 = __half22float2(h1);
    a = f0.x; b = f0.y; c = f1.x; d = f1.y;
}

__device__ __forceinline__ uint2 pack4(float a, float b, float c, float d)
{
    __half2 h0 = __floats2half2_rn(a, b);
    __half2 h1 = __floats2half2_rn(c, d);
    uint2 u;
    u.x = *(unsigned*)&h0;
    u.y = *(unsigned*)&h1;
    return u;
}

// Full-warp inclusive scan (all 32 lanes execute; no partial masks).
__device__ __forceinline__ int warp_incl_scan(int x, int lane)
{
    #pragma unroll
    for (int o = 1; o < 32; o <<= 1) {
        int y = __shfl_up_sync(0xffffffffu, x, o);
        if (lane >= o) x += y;
    }
    return x;
}

// ---------------- kernels ----------------

__global__ void k_init()
{
    int i = blockIdx.x * blockDim.x + threadIdx.x;
    if (i < N_NODES) {
        g_deg[i] = 0.0f;
        g_cnt[i] = 0;
        g_cur[i] = 0;
    }
    if (i < DIM) {
        g_colsum[i] = 0.0f;
        g_colsq[i]  = 0.0f;
    }
}

// Histogram counts AND float degree in one pass.
__global__ void k_hist(const int* __restrict__ erow, const float* __restrict__ eval)
{
    int e = blockIdx.x * blockDim.x + threadIdx.x;
    if (e < N_EDGES) {
        int r = erow[e];
        atomicAdd(&g_cnt[r], 1);
        atomicAdd(&g_deg[r], eval[e]);
    }
}

// x0 = R * deg^(-1/2) stored fp16, zero d_out (acc), and canonicalize deg (0 -> 1).
__global__ void k_initx(const float4* __restrict__ R, float4* __restrict__ acc)
{
    int i = blockIdx.x * blockDim.x + threadIdx.x;
    if (i < N_NODES * 32) {
        int node = i >> 5;
        float d = g_deg[node];
        if (d == 0.0f) d = 1.0f;
        if ((i & 31) == 0) g_deg[node] = d;   // all writers store identical value
        float s = rsqrtf(d);
        float4 r = R[i];
        g_x0[i] = pack4(r.x * s, r.y * s, r.z * s, r.w * s);
        acc[i]  = make_float4(0.f, 0.f, 0.f, 0.f);
    }
}

// ---- Three-phase parallel exclusive scan of g_cnt -> g_rowptr ----

// Phase A: per-block exclusive scan of 256 counts; write local prefixes + block totals.
__global__ __launch_bounds__(256) void k_scanA()
{
    __shared__ int wsum[32];                  // padded; only 8 used
    int tid  = threadIdx.x;
    int lane = tid & 31, wid = tid >> 5;
    int i    = blockIdx.x * 256 + tid;
    int v    = (i < N_NODES) ? g_cnt[i] : 0;

    int x = warp_incl_scan(v, lane);
    if (lane == 31) wsum[wid] = x;
    __syncthreads();
    if (wid == 0) {                           // full warp 0 executes
        int s = (lane < 8) ? wsum[lane] : 0;
        s = warp_incl_scan(s, lane);
        if (lane < 8) wsum[lane] = s;
    }
    __syncthreads();
    int excl = x - v + (wid ? wsum[wid - 1] : 0);
    if (i < N_NODES) g_rowptr[i] = excl;
    if (tid == 0) g_bsum[blockIdx.x] = wsum[7];
}

// Phase B: single block scans the NB block totals (exclusive).
__global__ __launch_bounds__(256) void k_scanB()
{
    __shared__ int wsum[32];                  // padded; only 8 used
    int tid  = threadIdx.x;
    int lane = tid & 31, wid = tid >> 5;
    int v    = (tid < NB) ? g_bsum[tid] : 0;

    int x = warp_incl_scan(v, lane);
    if (lane == 31) wsum[wid] = x;
    __syncthreads();
    if (wid == 0) {
        int s = (lane < 8) ? wsum[lane] : 0;
        s = warp_incl_scan(s, lane);
        if (lane < 8) wsum[lane] = s;
    }
    __syncthreads();
    if (tid < NB) g_boff[tid] = x - v + (wid ? wsum[wid - 1] : 0);
}

// Phase C: add block offsets.
__global__ __launch_bounds__(256) void k_scanC()
{
    int i = blockIdx.x * 256 + threadIdx.x;
    if (i < N_NODES) g_rowptr[i] += g_boff[blockIdx.x];
    if (i == 0) g_rowptr[N_NODES] = N_EDGES;
}

__global__ void k_scatter(const int* __restrict__ erow, const int* __restrict__ ecol,
                          const float* __restrict__ eval)
{
    int e = blockIdx.x * blockDim.x + threadIdx.x;
    if (e < N_EDGES) {
        int r = erow[e];
        int p = g_rowptr[r] + atomicAdd(&g_cur[r], 1);
        g_edge[p] = make_int2(ecol[e], __float_as_int(eval[e]));
    }
}

// One warp per row. Warp-uniform packed edge loads (coalescer broadcasts).
// Unroll-8 for 8 outstanding 256B gathers per batch. fp16 gathers, fp32 math.
__global__ __launch_bounds__(256) void k_spmm(int flip, float4* __restrict__ acc,
                                              float w, int last)
{
    int gtid = blockIdx.x * blockDim.x + threadIdx.x;
    int row  = gtid >> 5;
    int lane = threadIdx.x & 31;
    if (row >= N_NODES) return;

    const uint2* __restrict__ xin  = flip ? g_x1 : g_x0;
    uint2*       __restrict__ xout = flip ? g_x0 : g_x1;

    int s = g_rowptr[row];
    int e = g_rowptr[row + 1];

    float ax = 0.f, ay = 0.f, az = 0.f, aw = 0.f;

    int j = s;
    for (; j + 8 <= e; j += 8) {
        int2 ed[8];
        uint2 p[8];
        #pragma unroll
        for (int k = 0; k < 8; k++) ed[k] = g_edge[j + k];
        #pragma unroll
        for (int k = 0; k < 8; k++) p[k] = xin[ed[k].x * 32 + lane];
        #pragma unroll
        for (int k = 0; k < 8; k++) {
            float v = __int_as_float(ed[k].y);
            float x0, y0, z0, w0;
            unpack4(p[k], x0, y0, z0, w0);
            ax += v * x0; ay += v * y0; az += v * z0; aw += v * w0;
        }
    }
    if (j + 4 <= e) {
        int2 ed[4];
        uint2 p[4];
        #pragma unroll
        for (int k = 0; k < 4; k++) ed[k] = g_edge[j + k];
        #pragma unroll
        for (int k = 0; k < 4; k++) p[k] = xin[ed[k].x * 32 + lane];
        #pragma unroll
        for (int k = 0; k < 4; k++) {
            float v = __int_as_float(ed[k].y);
            float x0, y0, z0, w0;
            unpack4(p[k], x0, y0, z0, w0);
            ax += v * x0; ay += v * y0; az += v * z0; aw += v * w0;
        }
        j += 4;
    }
    for (; j < e; j++) {
        int2 ed = g_edge[j];
        float v = __int_as_float(ed.y);
        uint2 p = xin[ed.x * 32 + lane];
        float x0, y0, z0, w0;
        unpack4(p, x0, y0, z0, w0);
        ax += v * x0; ay += v * y0; az += v * z0; aw += v * w0;
    }

    float id = 1.0f / g_deg[row];
    ax *= id; ay *= id; az *= id; aw *= id;

    float ss = ax * ax + ay * ay + az * az + aw * aw;
    #pragma unroll
    for (int o = 16; o; o >>= 1) ss += __shfl_xor_sync(0xffffffffu, ss, o);

    float nrm = fmaxf(sqrtf(ss), EPSN);
    float sc  = w / nrm;

    int base = row * 32 + lane;
    if (!last) {
        xout[base] = pack4(ax * XSCALE, ay * XSCALE, az * XSCALE, aw * XSCALE);
    }
    float4 a = acc[base];
    acc[base] = make_float4(a.x + sc * ax, a.y + sc * ay, a.z + sc * az, a.w + sc * aw);
}

// Per-column sum and sum-of-squares partial reduction.
__global__ void k_colreduce(const float* __restrict__ acc)
{
    int c = threadIdx.x;
    float s = 0.f, q = 0.f;
    for (int r = blockIdx.x; r < N_NODES; r += gridDim.x) {
        float v = acc[r * DIM + c];
        s += v;
        q += v * v;
    }
    atomicAdd(&g_colsum[c], s);
    atomicAdd(&g_colsq[c], q);
}

__global__ void k_std(float* __restrict__ out)
{
    int i = blockIdx.x * blockDim.x + threadIdx.x;
    if (i < N_NODES * DIM) {
        int c = i & (DIM - 1);
        const float n = (float)N_NODES;
        float mean = g_colsum[c] / n;
        float var  = (g_colsq[c] - n * mean * mean) / (n - 1.0f);
        var = fmaxf(var, 0.0f);
        float sd = sqrtf(var);
        if (sd == 0.0f) sd = 1.0f;
        out[i] = (out[i] - mean) / sd;
    }
}

// ---------------- launcher ----------------

extern "C" void kernel_launch(void* const* d_in, const int* in_sizes, int n_in,
                              void* d_out, int out_size)
{
    const int*   erow = (const int*)d_in[0];
    const int*   ecol = (const int*)d_in[1];
    const float* eval = (const float*)d_in[2];
    const float* R    = (const float*)d_in[3];
    float*       out  = (float*)d_out;

    const float W[4] = {1.0f, 1.0f, 7.81f, 45.28f};

    const int warp_blocks = (N_NODES * 32 + 255) / 256;

    k_init<<<(N_NODES + 255) / 256, 256>>>();
    k_hist<<<(N_EDGES + 255) / 256, 256>>>(erow, eval);
    k_initx<<<(N_NODES * 32 + 255) / 256, 256>>>((const float4*)R, (float4*)d_out);
    k_scanA<<<NB, 256>>>();
    k_scanB<<<1, 256>>>();
    k_scanC<<<NB, 256>>>();
    k_scatter<<<(N_EDGES + 255) / 256, 256>>>(erow, ecol, eval);

    for (int i = 0; i < 4; i++) {
        k_spmm<<<warp_blocks, 256>>>(i & 1, (float4*)d_out, W[i], i == 3);
    }

    k_colreduce<<<256, DIM>>>(out);
    k_std<<<(N_NODES * DIM + 255) / 256, 256>>>(out);
}

// round 8
// speedup vs baseline: 1.8139x; 1.2688x over previous
#include <cuda_runtime.h>
#include <cuda_fp16.h>

#define N_NODES 50000
#define N_EDGES 800000
#define DIM     128
#define EPSN    1e-12f
#define XSCALE  8.0f        // per-iteration rescale; cancels exactly in the combine
#define NB      ((N_NODES + 255) / 256)   // 196 scan blocks

// ---------------- static device scratch (no allocations allowed) ----------------
__device__ float  g_deg[N_NODES];
__device__ int    g_cnt[N_NODES];
__device__ int    g_cur[N_NODES];
__device__ int    g_rowptr[N_NODES + 1];  // partial (per-block) prefixes; add g_boff
__device__ int    g_bsum[NB];
__device__ int    g_boff[NB];
__device__ int2   g_edge[N_EDGES];        // packed (col, float_as_int(val))
__device__ uint2  g_xa[N_NODES * 32];     // x0   (fp16, 4 halves per uint2)
__device__ uint2  g_xb[N_NODES * 32];     // x1
__device__ uint2  g_xc[N_NODES * 32];     // x2
__device__ uint2  g_xd[N_NODES * 32];     // x3
__device__ float  g_sc0[N_NODES];         // per-row combine scales for iters 0..2
__device__ float  g_sc1[N_NODES];
__device__ float  g_sc2[N_NODES];
__device__ float  g_colsum[DIM];
__device__ float  g_colsq[DIM];

// ---------------- helpers ----------------
__device__ __forceinline__ void unpack4(uint2 p, float& a, float& b, float& c, float& d)
{
    __half2 h0 = *(__half2*)&p.x;
    __half2 h1 = *(__half2*)&p.y;
    float2 f0 = __half22float2(h0);
    float2 f1 = __half22float2(h1);
    a = f0.x; b = f0.y; c = f1.x; d = f1.y;
}

__device__ __forceinline__ uint2 pack4(float a, float b, float c, float d)
{
    __half2 h0 = __floats2half2_rn(a, b);
    __half2 h1 = __floats2half2_rn(c, d);
    uint2 u;
    u.x = *(unsigned*)&h0;
    u.y = *(unsigned*)&h1;
    return u;
}

__device__ __forceinline__ int warp_incl_scan(int x, int lane)
{
    #pragma unroll
    for (int o = 1; o < 32; o <<= 1) {
        int y = __shfl_up_sync(0xffffffffu, x, o);
        if (lane >= o) x += y;
    }
    return x;
}

// Gather-accumulate one row's SpMM sum (raw, pre-invdeg). Warp-collective.
__device__ __forceinline__ void row_accum(const uint2* __restrict__ xin,
                                          int s, int e, int lane,
                                          float& ax, float& ay, float& az, float& aw)
{
    int j = s;
    for (; j + 8 <= e; j += 8) {
        int2 ed[8];
        uint2 p[8];
        #pragma unroll
        for (int k = 0; k < 8; k++) ed[k] = g_edge[j + k];
        #pragma unroll
        for (int k = 0; k < 8; k++) p[k] = xin[ed[k].x * 32 + lane];
        #pragma unroll
        for (int k = 0; k < 8; k++) {
            float v = __int_as_float(ed[k].y);
            float x0, y0, z0, w0;
            unpack4(p[k], x0, y0, z0, w0);
            ax += v * x0; ay += v * y0; az += v * z0; aw += v * w0;
        }
    }
    if (j + 4 <= e) {
        int2 ed[4];
        uint2 p[4];
        #pragma unroll
        for (int k = 0; k < 4; k++) ed[k] = g_edge[j + k];
        #pragma unroll
        for (int k = 0; k < 4; k++) p[k] = xin[ed[k].x * 32 + lane];
        #pragma unroll
        for (int k = 0; k < 4; k++) {
            float v = __int_as_float(ed[k].y);
            float x0, y0, z0, w0;
            unpack4(p[k], x0, y0, z0, w0);
            ax += v * x0; ay += v * y0; az += v * z0; aw += v * w0;
        }
        j += 4;
    }
    for (; j < e; j++) {
        int2 ed = g_edge[j];
        float v = __int_as_float(ed.y);
        uint2 p = xin[ed.x * 32 + lane];
        float x0, y0, z0, w0;
        unpack4(p, x0, y0, z0, w0);
        ax += v * x0; ay += v * y0; az += v * z0; aw += v * w0;
    }
}

// ---------------- kernels ----------------

__global__ void k_init()
{
    int i = blockIdx.x * blockDim.x + threadIdx.x;
    if (i < N_NODES) {
        g_deg[i] = 0.0f;
        g_cnt[i] = 0;
        g_cur[i] = 0;
    }
    if (i < DIM) {
        g_colsum[i] = 0.0f;
        g_colsq[i]  = 0.0f;
    }
}

__global__ void k_hist(const int* __restrict__ erow, const float* __restrict__ eval)
{
    int e = blockIdx.x * blockDim.x + threadIdx.x;
    if (e < N_EDGES) {
        int r = erow[e];
        atomicAdd(&g_cnt[r], 1);
        atomicAdd(&g_deg[r], eval[e]);
    }
}

// Phase A: per-block exclusive scan of counts; also canonicalize deg (0 -> 1).
__global__ __launch_bounds__(256) void k_scanA()
{
    __shared__ int wsum[32];
    int tid  = threadIdx.x;
    int lane = tid & 31, wid = tid >> 5;
    int i    = blockIdx.x * 256 + tid;
    int v    = (i < N_NODES) ? g_cnt[i] : 0;

    if (i < N_NODES && g_deg[i] == 0.0f) g_deg[i] = 1.0f;

    int x = warp_incl_scan(v, lane);
    if (lane == 31) wsum[wid] = x;
    __syncthreads();
    if (wid == 0) {
        int s = (lane < 8) ? wsum[lane] : 0;
        s = warp_incl_scan(s, lane);
        if (lane < 8) wsum[lane] = s;
    }
    __syncthreads();
    int excl = x - v + (wid ? wsum[wid - 1] : 0);
    if (i < N_NODES) g_rowptr[i] = excl;
    if (tid == 0) g_bsum[blockIdx.x] = wsum[7];
}

// Phase B: scan block totals -> g_boff. Also pre-compensate rowptr[N_NODES]
// so that rowptr[N] + boff[N>>8] == N_EDGES at the consumers.
__global__ __launch_bounds__(256) void k_scanB()
{
    __shared__ int wsum[32];
    int tid  = threadIdx.x;
    int lane = tid & 31, wid = tid >> 5;
    int v    = (tid < NB) ? g_bsum[tid] : 0;

    int x = warp_incl_scan(v, lane);
    if (lane == 31) wsum[wid] = x;
    __syncthreads();
    if (wid == 0) {
        int s = (lane < 8) ? wsum[lane] : 0;
        s = warp_incl_scan(s, lane);
        if (lane < 8) wsum[lane] = s;
    }
    __syncthreads();
    int myoff = x - v + (wid ? wsum[wid - 1] : 0);
    if (tid < NB) g_boff[tid] = myoff;
    if (tid == (N_NODES >> 8)) g_rowptr[N_NODES] = N_EDGES - myoff;
}

// Scatter edges into CSR order, then grid-stride init of x0 = R * deg^(-1/2).
__global__ void k_scatter(const int* __restrict__ erow, const int* __restrict__ ecol,
                          const float* __restrict__ eval, const float4* __restrict__ R)
{
    int e = blockIdx.x * blockDim.x + threadIdx.x;
    if (e < N_EDGES) {
        int r = erow[e];
        int p = g_rowptr[r] + g_boff[r >> 8] + atomicAdd(&g_cur[r], 1);
        g_edge[p] = make_int2(ecol[e], __float_as_int(eval[e]));
    }
    // phase 2: x0 init (deg already canonicalized in scanA)
    int total = N_NODES * 32;
    for (int i = e; i < total; i += gridDim.x * blockDim.x) {
        int node = i >> 5;
        float s = rsqrtf(g_deg[node]);
        float4 r = R[i];
        g_xa[i] = pack4(r.x * s, r.y * s, r.z * s, r.w * s);
    }
}

// SpMM iters 0..2: gather, inv-deg, norm; store x_{i+1} (fp16, XSCALE) + combine scale.
__global__ __launch_bounds__(256) void k_spmm(const uint2* __restrict__ xin,
                                              uint2* __restrict__ xout,
                                              float* __restrict__ scarr, float w)
{
    int gtid = blockIdx.x * blockDim.x + threadIdx.x;
    int row  = gtid >> 5;
    int lane = threadIdx.x & 31;
    if (row >= N_NODES) return;

    int s = g_rowptr[row]     + g_boff[row >> 8];
    int e = g_rowptr[row + 1] + g_boff[(row + 1) >> 8];

    float ax = 0.f, ay = 0.f, az = 0.f, aw = 0.f;
    row_accum(xin, s, e, lane, ax, ay, az, aw);

    float id = 1.0f / g_deg[row];
    ax *= id; ay *= id; az *= id; aw *= id;

    float ss = ax * ax + ay * ay + az * az + aw * aw;
    #pragma unroll
    for (int o = 16; o; o >>= 1) ss += __shfl_xor_sync(0xffffffffu, ss, o);

    float nrm = fmaxf(sqrtf(ss), EPSN);
    if (lane == 0) scarr[row] = w / (nrm * XSCALE);

    xout[row * 32 + lane] = pack4(ax * XSCALE, ay * XSCALE, az * XSCALE, aw * XSCALE);
}

// Last SpMM: iter-3 gather + combine all four weighted terms + column stats.
__global__ __launch_bounds__(256) void k_spmm_last(float4* __restrict__ out, float w)
{
    __shared__ float cs[DIM];
    __shared__ float cq[DIM];

    int tid  = threadIdx.x;
    int gtid = blockIdx.x * blockDim.x + tid;
    int row  = gtid >> 5;
    int lane = tid & 31;

    if (tid < DIM) { cs[tid] = 0.0f; cq[tid] = 0.0f; }
    __syncthreads();

    if (row < N_NODES) {
        int s = g_rowptr[row]     + g_boff[row >> 8];
        int e = g_rowptr[row + 1] + g_boff[(row + 1) >> 8];

        float ax = 0.f, ay = 0.f, az = 0.f, aw = 0.f;
        row_accum(g_xd, s, e, lane, ax, ay, az, aw);

        float id = 1.0f / g_deg[row];
        ax *= id; ay *= id; az *= id; aw *= id;

        float ss = ax * ax + ay * ay + az * az + aw * aw;
        #pragma unroll
        for (int o = 16; o; o >>= 1) ss += __shfl_xor_sync(0xffffffffu, ss, o);

        float nrm = fmaxf(sqrtf(ss), EPSN);
        float sc3 = w / nrm;

        int base = row * 32 + lane;
        float s0 = g_sc0[row], s1 = g_sc1[row], s2 = g_sc2[row];

        float x1, y1, z1, w1, x2, y2, z2, w2, x3, y3, z3, w3;
        unpack4(g_xb[base], x1, y1, z1, w1);
        unpack4(g_xc[base], x2, y2, z2, w2);
        unpack4(g_xd[base], x3, y3, z3, w3);

        float ox = s0 * x1 + s1 * x2 + s2 * x3 + sc3 * ax;
        float oy = s0 * y1 + s1 * y2 + s2 * y3 + sc3 * ay;
        float oz = s0 * z1 + s1 * z2 + s2 * z3 + sc3 * az;
        float ow = s0 * w1 + s1 * w2 + s2 * w3 + sc3 * aw;

        out[base] = make_float4(ox, oy, oz, ow);

        int c = 4 * lane;
        atomicAdd(&cs[c],     ox); atomicAdd(&cq[c],     ox * ox);
        atomicAdd(&cs[c + 1], oy); atomicAdd(&cq[c + 1], oy * oy);
        atomicAdd(&cs[c + 2], oz); atomicAdd(&cq[c + 2], oz * oz);
        atomicAdd(&cs[c + 3], ow); atomicAdd(&cq[c + 3], ow * ow);
    }
    __syncthreads();
    if (tid < DIM) {
        atomicAdd(&g_colsum[tid], cs[tid]);
        atomicAdd(&g_colsq[tid],  cq[tid]);
    }
}

__global__ void k_std(float* __restrict__ out)
{
    int i = blockIdx.x * blockDim.x + threadIdx.x;
    if (i < N_NODES * DIM) {
        int c = i & (DIM - 1);
        const float n = (float)N_NODES;
        float mean = g_colsum[c] / n;
        float var  = (g_colsq[c] - n * mean * mean) / (n - 1.0f);
        var = fmaxf(var, 0.0f);
        float sd = sqrtf(var);
        if (sd == 0.0f) sd = 1.0f;
        out[i] = (out[i] - mean) / sd;
    }
}

// ---------------- launcher ----------------

extern "C" void kernel_launch(void* const* d_in, const int* in_sizes, int n_in,
                              void* d_out, int out_size)
{
    const int*   erow = (const int*)d_in[0];
    const int*   ecol = (const int*)d_in[1];
    const float* eval = (const float*)d_in[2];
    const float* R    = (const float*)d_in[3];
    float*       out  = (float*)d_out;

    const int warp_blocks = (N_NODES * 32 + 255) / 256;

    // Pointer views of __device__ arrays for kernel parameters.
    uint2 *xa, *xb, *xc, *xd;
    float *sc0, *sc1, *sc2;
    cudaGetSymbolAddress((void**)&xa,  g_xa);
    cudaGetSymbolAddress((void**)&xb,  g_xb);
    cudaGetSymbolAddress((void**)&xc,  g_xc);
    cudaGetSymbolAddress((void**)&xd,  g_xd);
    cudaGetSymbolAddress((void**)&sc0, g_sc0);
    cudaGetSymbolAddress((void**)&sc1, g_sc1);
    cudaGetSymbolAddress((void**)&sc2, g_sc2);

    k_init<<<(N_NODES + 255) / 256, 256>>>();                                   // 1
    k_hist<<<(N_EDGES + 255) / 256, 256>>>(erow, eval);                         // 2
    k_scanA<<<NB, 256>>>();                                                     // 3
    k_scanB<<<1, 256>>>();                                                      // 4
    k_scatter<<<(N_EDGES + 255) / 256, 256>>>(erow, ecol, eval,
                                              (const float4*)R);                // 5
    k_spmm<<<warp_blocks, 256>>>(xa, xb, sc0, 1.0f);                            // 6
    k_spmm<<<warp_blocks, 256>>>(xb, xc, sc1, 1.0f);                            // 7
    k_spmm<<<warp_blocks, 256>>>(xc, xd, sc2, 7.81f);                           // 8
    k_spmm_last<<<warp_blocks, 256>>>((float4*)d_out, 45.28f);                  // 9
    k_std<<<(N_NODES * DIM + 255) / 256, 256>>>(out);                           // 10
}